// round 1
// baseline (speedup 1.0000x reference)
#include <cuda_runtime.h>
#include <cstdint>
#include <cstddef>

#define NB   4
#define LEN  2000
#define LP   2048
#define KDIM 512
#define HDIM 256

// ---------------- scratch (static device globals; no runtime alloc) ----------------
__device__ float g_scale[2];                       // g/||V||_F for Q and K
__device__ float g_P1 [(size_t)NB * LP * KDIM];    // fc(X,Q)*h   (pad rows = 0)
__device__ float g_A1Y[(size_t)NB * LP * KDIM];    // fc(Y,K)
__device__ float g_P2 [(size_t)NB * LP * KDIM];    // fc(Y,Q)*h
__device__ float g_A2X[(size_t)NB * LP * KDIM];    // fc(X,K)
__device__ float g_A1 [(size_t)NB * LP * LP];      // A1[b,v,q]
__device__ float g_A2 [(size_t)NB * LP * LP];      // A2[b,q,v]
__device__ float g_w1 [NB * LEN];
__device__ float g_w2 [NB * LEN];
__device__ float g_part[8 * NB * KDIM];            // q-split partial pooled sums

// ---------------- kernel 1: weight-norm scales ----------------
__global__ void norm_kernel(const float* __restrict__ Qv, const float* __restrict__ Qg,
                            const float* __restrict__ Kv, const float* __restrict__ Kg)
{
    const float* V = blockIdx.x ? Kv : Qv;
    const float* G = blockIdx.x ? Kg : Qg;
    __shared__ float red[256];
    float s = 0.f;
    for (int i = threadIdx.x; i < KDIM * HDIM; i += 256) {
        float v = V[i];
        s += v * v;
    }
    red[threadIdx.x] = s;
    __syncthreads();
    for (int st = 128; st > 0; st >>= 1) {
        if (threadIdx.x < st) red[threadIdx.x] += red[threadIdx.x + st];
        __syncthreads();
    }
    if (threadIdx.x == 0) g_scale[blockIdx.x] = G[0] / sqrtf(red[0]);
}

// ---------------- kernel 2: FC projection  out = relu(scale * X@V^T + b) [* h] ----------------
// M = NB*LP (padded rows -> 0), N = KDIM, K = HDIM. 128x128x8 tile, 8x8/thread.
__global__ __launch_bounds__(256) void fc_kernel(
    const float* __restrict__ Xin, const float* __restrict__ W,
    const float* __restrict__ bias, const float* __restrict__ hvec,
    int scaleIdx, int useH, int outSel)
{
    float* out = (outSel == 0) ? g_P1 : (outSel == 1) ? g_A1Y : (outSel == 2) ? g_P2 : g_A2X;

    __shared__ float As[8][128];
    __shared__ float Bs[8][128];

    const int tid = threadIdx.x;
    const int tx = tid & 15, ty = tid >> 4;
    const int rowBase = blockIdx.y * 128;
    const int colBase = blockIdx.x * 128;
    const int lr = tid >> 1;
    const int lq = (tid & 1) << 2;

    const int  m  = rowBase + lr;
    const int  bb = m >> 11;
    const int  ll = m & (LP - 1);
    const bool avalid = ll < LEN;
    const float* Aptr = Xin + ((size_t)bb * LEN + ll) * HDIM + lq;
    const float* Bptr = W + (size_t)(colBase + lr) * HDIM + lq;

    float acc[8][8];
#pragma unroll
    for (int i = 0; i < 8; i++)
#pragma unroll
        for (int j = 0; j < 8; j++) acc[i][j] = 0.f;

    float4 av = avalid ? *(const float4*)Aptr : make_float4(0.f, 0.f, 0.f, 0.f);
    float4 bv = *(const float4*)Bptr;

    for (int k0 = 0; k0 < HDIM; k0 += 8) {
        As[lq + 0][lr] = av.x; As[lq + 1][lr] = av.y; As[lq + 2][lr] = av.z; As[lq + 3][lr] = av.w;
        Bs[lq + 0][lr] = bv.x; Bs[lq + 1][lr] = bv.y; Bs[lq + 2][lr] = bv.z; Bs[lq + 3][lr] = bv.w;
        __syncthreads();
        if (k0 + 8 < HDIM) {
            av = avalid ? *(const float4*)(Aptr + k0 + 8) : make_float4(0.f, 0.f, 0.f, 0.f);
            bv = *(const float4*)(Bptr + k0 + 8);
        }
#pragma unroll
        for (int k = 0; k < 8; k++) {
            float4 a0 = *(const float4*)&As[k][ty * 8];
            float4 a1 = *(const float4*)&As[k][ty * 8 + 4];
            float4 b0 = *(const float4*)&Bs[k][tx * 8];
            float4 b1 = *(const float4*)&Bs[k][tx * 8 + 4];
            float a[8] = {a0.x, a0.y, a0.z, a0.w, a1.x, a1.y, a1.z, a1.w};
            float b[8] = {b0.x, b0.y, b0.z, b0.w, b1.x, b1.y, b1.z, b1.w};
#pragma unroll
            for (int i = 0; i < 8; i++)
#pragma unroll
                for (int j = 0; j < 8; j++)
                    acc[i][j] = fmaf(a[i], b[j], acc[i][j]);
        }
        __syncthreads();
    }

    const float scale = g_scale[scaleIdx];
    float bn[8], hn[8];
#pragma unroll
    for (int j = 0; j < 8; j++) {
        int n = colBase + tx * 8 + j;
        bn[j] = bias[n];
        hn[j] = useH ? hvec[n] : 1.0f;
    }
#pragma unroll
    for (int i = 0; i < 8; i++) {
        int r = rowBase + ty * 8 + i;
        bool valid = (r & (LP - 1)) < LEN;
        float vals[8];
#pragma unroll
        for (int j = 0; j < 8; j++) {
            float v = fmaxf(scale * acc[i][j] + bn[j], 0.f) * hn[j];
            vals[j] = valid ? v : 0.f;
        }
        float* cp = out + (size_t)r * KDIM + colBase + tx * 8;
        *(float4*)cp       = make_float4(vals[0], vals[1], vals[2], vals[3]);
        *(float4*)(cp + 4) = make_float4(vals[4], vals[5], vals[6], vals[7]);
    }
}

// ---------------- kernel 3: attention Gram matrix  C[b] = A[b] @ B[b]^T + h_bias ----------------
// M = N = LP, K = KDIM, per-batch via blockIdx.z. No bounds checks (padded).
__global__ __launch_bounds__(256) void att_gemm(const float* __restrict__ hbias_p, int sel)
{
    const float* Ag = sel ? g_P2  : g_P1;
    const float* Bg = sel ? g_A2X : g_A1Y;
    float*       Cg = sel ? g_A2  : g_A1;

    const int bz = blockIdx.z;
    const float* A  = Ag + (size_t)bz * LP * KDIM;
    const float* Bm = Bg + (size_t)bz * LP * KDIM;
    float*       C  = Cg + (size_t)bz * LP * LP;

    __shared__ float As[8][128];
    __shared__ float Bs[8][128];

    const int tid = threadIdx.x;
    const int tx = tid & 15, ty = tid >> 4;
    const int rowBase = blockIdx.y * 128;
    const int colBase = blockIdx.x * 128;
    const int lr = tid >> 1;
    const int lq = (tid & 1) << 2;

    const float* Aptr = A  + (size_t)(rowBase + lr) * KDIM + lq;
    const float* Bptr = Bm + (size_t)(colBase + lr) * KDIM + lq;

    float acc[8][8];
#pragma unroll
    for (int i = 0; i < 8; i++)
#pragma unroll
        for (int j = 0; j < 8; j++) acc[i][j] = 0.f;

    float4 av = *(const float4*)Aptr;
    float4 bv = *(const float4*)Bptr;

    for (int k0 = 0; k0 < KDIM; k0 += 8) {
        As[lq + 0][lr] = av.x; As[lq + 1][lr] = av.y; As[lq + 2][lr] = av.z; As[lq + 3][lr] = av.w;
        Bs[lq + 0][lr] = bv.x; Bs[lq + 1][lr] = bv.y; Bs[lq + 2][lr] = bv.z; Bs[lq + 3][lr] = bv.w;
        __syncthreads();
        if (k0 + 8 < KDIM) {
            av = *(const float4*)(Aptr + k0 + 8);
            bv = *(const float4*)(Bptr + k0 + 8);
        }
#pragma unroll
        for (int k = 0; k < 8; k++) {
            float4 a0 = *(const float4*)&As[k][ty * 8];
            float4 a1 = *(const float4*)&As[k][ty * 8 + 4];
            float4 b0 = *(const float4*)&Bs[k][tx * 8];
            float4 b1 = *(const float4*)&Bs[k][tx * 8 + 4];
            float a[8] = {a0.x, a0.y, a0.z, a0.w, a1.x, a1.y, a1.z, a1.w};
            float b[8] = {b0.x, b0.y, b0.z, b0.w, b1.x, b1.y, b1.z, b1.w};
#pragma unroll
            for (int i = 0; i < 8; i++)
#pragma unroll
                for (int j = 0; j < 8; j++)
                    acc[i][j] = fmaf(a[i], b[j], acc[i][j]);
        }
        __syncthreads();
    }

    const float bias = *hbias_p;
#pragma unroll
    for (int i = 0; i < 8; i++) {
        size_t r = (size_t)(rowBase + ty * 8 + i);
        float* cp = C + r * LP + colBase + tx * 8;
        *(float4*)cp       = make_float4(acc[i][0] + bias, acc[i][1] + bias,
                                         acc[i][2] + bias, acc[i][3] + bias);
        *(float4*)(cp + 4) = make_float4(acc[i][4] + bias, acc[i][5] + bias,
                                         acc[i][6] + bias, acc[i][7] + bias);
    }
}

// ---------------- kernel 4: per-column online softmax reduction ----------------
// mat 0: reduce A1 over rows v (weight mask1), outer mask2 -> w1[q]
// mat 1: reduce A2 over rows q (weight mask2), outer mask1 -> w2[v]
__global__ void col_softmax(const float* __restrict__ mask1, const float* __restrict__ mask2)
{
    const int mat = blockIdx.z;
    const float* A     = mat ? g_A2  : g_A1;
    const float* rmask = mat ? mask2 : mask1;
    const float* cmask = mat ? mask1 : mask2;
    float*       wout  = mat ? g_w2  : g_w1;

    const int b  = blockIdx.y;
    const int tx = threadIdx.x, ty = threadIdx.y;
    const int q  = blockIdx.x * 32 + tx;
    const bool qv = q < LEN;
    const float* Ab = A + (size_t)b * LP * LP;

    float m = -1e30f, den = 0.f, num = 0.f;
    if (qv) {
        for (int v = ty; v < LEN; v += 8) {
            float x = Ab[(size_t)v * LP + q];
            float w = rmask[b * LEN + v];
            float nm = fmaxf(m, x);
            float c = __expf(m - nm);
            float e = __expf(x - nm);
            den = den * c + e;
            num = num * c + w * e;
            m = nm;
        }
    }
    __shared__ float sm[8][32], sd[8][32], sn[8][32];
    sm[ty][tx] = m; sd[ty][tx] = den; sn[ty][tx] = num;
    __syncthreads();
    if (ty == 0 && qv) {
        float M = sm[0][tx], D = sd[0][tx], Nn = sn[0][tx];
#pragma unroll
        for (int i = 1; i < 8; i++) {
            float mi = sm[i][tx];
            float nm = fmaxf(M, mi);
            float c1 = __expf(M - nm), c2 = __expf(mi - nm);
            D  = D  * c1 + sd[i][tx] * c2;
            Nn = Nn * c1 + sn[i][tx] * c2;
            M = nm;
        }
        wout[b * LEN + q] = cmask[b * LEN + q] * Nn / D;
    }
}

// ---------------- kernel 5: pooled partial GEMVs (q-split to fill the chip) ----------------
__global__ void pooled_partial()
{
    const int b = blockIdx.y, sp = blockIdx.z;
    const int k = blockIdx.x * 128 + threadIdx.x;
    const int q0 = sp * (LEN / 8), q1 = q0 + (LEN / 8);
    const float* P = g_A1Y + (size_t)b * LP * KDIM;
    const float* Q = g_A2X + (size_t)b * LP * KDIM;
    float acc = 0.f;
    for (int q = q0; q < q1; q++) acc = fmaf(g_w1[b * LEN + q], P[(size_t)q * KDIM + k], acc);
    for (int q = q0; q < q1; q++) acc = fmaf(g_w2[b * LEN + q], Q[(size_t)q * KDIM + k], acc);
    g_part[(sp * NB + b) * KDIM + k] = acc;
}

// ---------------- kernel 6: batch layernorm over B=4 ----------------
__global__ void ln_kernel(const float* __restrict__ gamma, const float* __restrict__ beta,
                          float* __restrict__ out)
{
    const int k = blockIdx.x * 256 + threadIdx.x;
    float p[NB];
#pragma unroll
    for (int b = 0; b < NB; b++) {
        float s = 0.f;
#pragma unroll
        for (int sp = 0; sp < 8; sp++) s += g_part[(sp * NB + b) * KDIM + k];
        p[b] = s * (1.0f / LEN);
    }
    float mu = 0.25f * (p[0] + p[1] + p[2] + p[3]);
    float var = 0.f;
#pragma unroll
    for (int b = 0; b < NB; b++) { float d = p[b] - mu; var += d * d; }
    var *= 0.25f;
    float inv = rsqrtf(var + 1e-5f);
#pragma unroll
    for (int b = 0; b < NB; b++)
        out[b * KDIM + k] = gamma[k] * (p[b] - mu) * inv + beta[k];
}

// ---------------- launch ----------------
extern "C" void kernel_launch(void* const* d_in, const int* in_sizes, int n_in,
                              void* d_out, int out_size)
{
    const float* X      = (const float*)d_in[0];
    const float* Y      = (const float*)d_in[1];
    const float* mask1  = (const float*)d_in[2];
    const float* mask2  = (const float*)d_in[3];
    const float* Qv     = (const float*)d_in[4];
    const float* Qg     = (const float*)d_in[5];
    const float* Qb     = (const float*)d_in[6];
    const float* Kv     = (const float*)d_in[7];
    const float* Kg     = (const float*)d_in[8];
    const float* Kb     = (const float*)d_in[9];
    const float* h_mat  = (const float*)d_in[10];
    const float* h_bias = (const float*)d_in[11];
    const float* gamma  = (const float*)d_in[12];
    const float* beta   = (const float*)d_in[13];
    float* out = (float*)d_out;

    norm_kernel<<<2, 256>>>(Qv, Qg, Kv, Kg);

    dim3 fcGrid(KDIM / 128, (NB * LP) / 128);
    fc_kernel<<<fcGrid, 256>>>(X, Qv, Qb, h_mat, 0, 1, 0);  // P1  = fc(X,Q)*h
    fc_kernel<<<fcGrid, 256>>>(Y, Kv, Kb, h_mat, 1, 0, 1);  // A1Y = fc(Y,K)
    fc_kernel<<<fcGrid, 256>>>(Y, Qv, Qb, h_mat, 0, 1, 2);  // P2  = fc(Y,Q)*h
    fc_kernel<<<fcGrid, 256>>>(X, Kv, Kb, h_mat, 1, 0, 3);  // A2X = fc(X,K)

    dim3 attGrid(LP / 128, LP / 128, NB);
    att_gemm<<<attGrid, 256>>>(h_bias, 0);                  // A1 = P1 @ A1Y^T + hb
    att_gemm<<<attGrid, 256>>>(h_bias, 1);                  // A2 = P2 @ A2X^T + hb

    col_softmax<<<dim3((LEN + 31) / 32, NB, 2), dim3(32, 8)>>>(mask1, mask2);
    pooled_partial<<<dim3(KDIM / 128, NB, 8), 128>>>();
    ln_kernel<<<KDIM / 256, 256>>>(gamma, beta, out);
}

// round 2
// speedup vs baseline: 1.8957x; 1.8957x over previous
#include <cuda_runtime.h>
#include <cstdint>
#include <cstddef>

#define NB   4
#define LEN  2000
#define LP   2048
#define KDIM 512
#define HDIM 256

// ---------------- scratch (static device globals; no runtime alloc) ----------------
__device__ float g_scale[2];                       // g/||V||_F for Q and K
__device__ float g_P1 [(size_t)NB * LP * KDIM];    // fc(X,Q)*h   (pad rows = 0)
__device__ float g_A1Y[(size_t)NB * LP * KDIM];    // fc(Y,K)
__device__ float g_P2 [(size_t)NB * LP * KDIM];    // fc(Y,Q)*h
__device__ float g_A2X[(size_t)NB * LP * KDIM];    // fc(X,K)
__device__ float g_A1 [(size_t)NB * LP * LP];      // A1[b,v,q]
__device__ float g_A2 [(size_t)NB * LP * LP];      // A2[b,q,v]
__device__ float g_w1 [NB * LEN];
__device__ float g_w2 [NB * LEN];
__device__ float g_part[8 * NB * KDIM];            // q-split partial pooled sums

// ---------------- helpers ----------------
__device__ __forceinline__ unsigned f2tf(float f) {
    unsigned u;
    asm("cvt.rna.tf32.f32 %0, %1;" : "=r"(u) : "f"(f));
    return u;
}
__device__ __forceinline__ float4 cvt4(float4 v) {
    return make_float4(__uint_as_float(f2tf(v.x)), __uint_as_float(f2tf(v.y)),
                       __uint_as_float(f2tf(v.z)), __uint_as_float(f2tf(v.w)));
}
__device__ __forceinline__ void mma_tf32(float* c, const unsigned* a, const unsigned* b) {
    asm volatile(
        "mma.sync.aligned.m16n8k8.row.col.f32.tf32.tf32.f32 "
        "{%0,%1,%2,%3}, {%4,%5,%6,%7}, {%8,%9}, {%0,%1,%2,%3};\n"
        : "+f"(c[0]), "+f"(c[1]), "+f"(c[2]), "+f"(c[3])
        : "r"(a[0]), "r"(a[1]), "r"(a[2]), "r"(a[3]), "r"(b[0]), "r"(b[1]));
}

#define SK 36   // smem row stride (32 k + 4 pad) -> conflict-free fragment loads

// ---------------- kernel 1: weight-norm scales ----------------
__global__ void norm_kernel(const float* __restrict__ Qv, const float* __restrict__ Qg,
                            const float* __restrict__ Kv, const float* __restrict__ Kg)
{
    const float* V = blockIdx.x ? Kv : Qv;
    const float* G = blockIdx.x ? Kg : Qg;
    __shared__ float red[256];
    float s = 0.f;
    for (int i = threadIdx.x; i < KDIM * HDIM; i += 256) {
        float v = V[i];
        s += v * v;
    }
    red[threadIdx.x] = s;
    __syncthreads();
    for (int st = 128; st > 0; st >>= 1) {
        if (threadIdx.x < st) red[threadIdx.x] += red[threadIdx.x + st];
        __syncthreads();
    }
    if (threadIdx.x == 0) g_scale[blockIdx.x] = G[0] / sqrtf(red[0]);
}

// ---------------- kernel 2: FC projection via tf32 MMA ----------------
// out = relu(scale * X@W^T + b) [* h].  M = NB*LP (pad rows -> 0), N=KDIM, K=HDIM.
// 128x128 tile, BK=32, 8 warps (2m x 4n), warp = 64x32, m16n8k8 frags.
__global__ __launch_bounds__(256) void fc_mma(
    const float* __restrict__ Xin, const float* __restrict__ W,
    const float* __restrict__ bias, const float* __restrict__ hvec,
    int scaleIdx, int useH, int outSel)
{
    float* out = (outSel == 0) ? g_P1 : (outSel == 1) ? g_A1Y : (outSel == 2) ? g_P2 : g_A2X;

    __shared__ float As[128 * SK];
    __shared__ float Bs[128 * SK];

    const int tid  = threadIdx.x;
    const int lane = tid & 31;
    const int warp = tid >> 5;
    const int wm = warp >> 2;          // 0..1 -> 64 rows
    const int wn = warp & 3;           // 0..3 -> 32 cols
    const int rowBase = blockIdx.y * 128;
    const int colBase = blockIdx.x * 128;

    // global load mapping: r = tile row (0..127), kc = starting k in {0,4}, j*8 strides
    const int r  = tid >> 1;
    const int kc = (tid & 1) << 2;

    const int  m  = rowBase + r;
    const int  bb = m >> 11;
    const int  ll = m & (LP - 1);
    const bool avalid = ll < LEN;
    const float* Aptr = Xin + ((size_t)bb * LEN + ll) * HDIM + kc;
    const float* Bptr = W + (size_t)(colBase + r) * HDIM + kc;

    float acc[4][4][4];
#pragma unroll
    for (int i = 0; i < 4; i++)
#pragma unroll
        for (int j = 0; j < 4; j++)
#pragma unroll
            for (int t = 0; t < 4; t++) acc[i][j][t] = 0.f;

    float4 pa[4], pb[4];
#pragma unroll
    for (int j = 0; j < 4; j++) {
        pa[j] = avalid ? *(const float4*)(Aptr + j * 8) : make_float4(0.f, 0.f, 0.f, 0.f);
        pb[j] = *(const float4*)(Bptr + j * 8);
    }

    const int NCH = HDIM / 32;
    for (int ch = 0; ch < NCH; ch++) {
#pragma unroll
        for (int j = 0; j < 4; j++) {
            *(float4*)&As[r * SK + kc + j * 8] = cvt4(pa[j]);
            *(float4*)&Bs[r * SK + kc + j * 8] = cvt4(pb[j]);
        }
        __syncthreads();
        if (ch + 1 < NCH) {
            int koff = (ch + 1) * 32;
#pragma unroll
            for (int j = 0; j < 4; j++) {
                pa[j] = avalid ? *(const float4*)(Aptr + koff + j * 8)
                               : make_float4(0.f, 0.f, 0.f, 0.f);
                pb[j] = *(const float4*)(Bptr + koff + j * 8);
            }
        }
#pragma unroll
        for (int ks = 0; ks < 4; ks++) {
            unsigned af[4][4], bf[4][2];
#pragma unroll
            for (int mf = 0; mf < 4; mf++) {
                const float* p = &As[(wm * 64 + mf * 16 + (lane >> 2)) * SK + ks * 8 + (lane & 3)];
                af[mf][0] = __float_as_uint(p[0]);
                af[mf][1] = __float_as_uint(p[8 * SK]);
                af[mf][2] = __float_as_uint(p[4]);
                af[mf][3] = __float_as_uint(p[8 * SK + 4]);
            }
#pragma unroll
            for (int nf = 0; nf < 4; nf++) {
                const float* p = &Bs[(wn * 32 + nf * 8 + (lane >> 2)) * SK + ks * 8 + (lane & 3)];
                bf[nf][0] = __float_as_uint(p[0]);
                bf[nf][1] = __float_as_uint(p[4]);
            }
#pragma unroll
            for (int mf = 0; mf < 4; mf++)
#pragma unroll
                for (int nf = 0; nf < 4; nf++)
                    mma_tf32(acc[mf][nf], af[mf], bf[nf]);
        }
        __syncthreads();
    }

    // epilogue
    const float scale = g_scale[scaleIdx];
#pragma unroll
    for (int mf = 0; mf < 4; mf++) {
        int row0 = rowBase + wm * 64 + mf * 16 + (lane >> 2);
        int row1 = row0 + 8;
        bool v0 = (row0 & (LP - 1)) < LEN;
        bool v1 = (row1 & (LP - 1)) < LEN;
#pragma unroll
        for (int nf = 0; nf < 4; nf++) {
            int col = colBase + wn * 32 + nf * 8 + (lane & 3) * 2;
            float b0 = bias[col], b1 = bias[col + 1];
            float h0 = useH ? hvec[col] : 1.f, h1 = useH ? hvec[col + 1] : 1.f;
            float* c = acc[mf][nf];
            float2 o0 = make_float2(
                v0 ? fmaxf(scale * c[0] + b0, 0.f) * h0 : 0.f,
                v0 ? fmaxf(scale * c[1] + b1, 0.f) * h1 : 0.f);
            float2 o1 = make_float2(
                v1 ? fmaxf(scale * c[2] + b0, 0.f) * h0 : 0.f,
                v1 ? fmaxf(scale * c[3] + b1, 0.f) * h1 : 0.f);
            *(float2*)&out[(size_t)row0 * KDIM + col] = o0;
            *(float2*)&out[(size_t)row1 * KDIM + col] = o1;
        }
    }
}

// ---------------- kernel 3: attention Gram matrix via tf32 MMA ----------------
// C[b] = A[b] @ B[b]^T + h_bias.  M = N = LP, K = KDIM. No bounds checks (padded zeros).
__global__ __launch_bounds__(256) void att_mma(const float* __restrict__ hbias_p, int sel)
{
    const float* Ag = sel ? g_P2  : g_P1;
    const float* Bg = sel ? g_A2X : g_A1Y;
    float*       Cg = sel ? g_A2  : g_A1;

    const int bz = blockIdx.z;
    const float* A  = Ag + (size_t)bz * LP * KDIM;
    const float* Bm = Bg + (size_t)bz * LP * KDIM;
    float*       C  = Cg + (size_t)bz * LP * LP;

    __shared__ float As[128 * SK];
    __shared__ float Bs[128 * SK];

    const int tid  = threadIdx.x;
    const int lane = tid & 31;
    const int warp = tid >> 5;
    const int wm = warp >> 2;
    const int wn = warp & 3;
    const int rowBase = blockIdx.y * 128;
    const int colBase = blockIdx.x * 128;

    const int r  = tid >> 1;
    const int kc = (tid & 1) << 2;

    const float* Aptr = A  + (size_t)(rowBase + r) * KDIM + kc;
    const float* Bptr = Bm + (size_t)(colBase + r) * KDIM + kc;

    float acc[4][4][4];
#pragma unroll
    for (int i = 0; i < 4; i++)
#pragma unroll
        for (int j = 0; j < 4; j++)
#pragma unroll
            for (int t = 0; t < 4; t++) acc[i][j][t] = 0.f;

    float4 pa[4], pb[4];
#pragma unroll
    for (int j = 0; j < 4; j++) {
        pa[j] = *(const float4*)(Aptr + j * 8);
        pb[j] = *(const float4*)(Bptr + j * 8);
    }

    const int NCH = KDIM / 32;
    for (int ch = 0; ch < NCH; ch++) {
#pragma unroll
        for (int j = 0; j < 4; j++) {
            *(float4*)&As[r * SK + kc + j * 8] = cvt4(pa[j]);
            *(float4*)&Bs[r * SK + kc + j * 8] = cvt4(pb[j]);
        }
        __syncthreads();
        if (ch + 1 < NCH) {
            int koff = (ch + 1) * 32;
#pragma unroll
            for (int j = 0; j < 4; j++) {
                pa[j] = *(const float4*)(Aptr + koff + j * 8);
                pb[j] = *(const float4*)(Bptr + koff + j * 8);
            }
        }
#pragma unroll
        for (int ks = 0; ks < 4; ks++) {
            unsigned af[4][4], bf[4][2];
#pragma unroll
            for (int mf = 0; mf < 4; mf++) {
                const float* p = &As[(wm * 64 + mf * 16 + (lane >> 2)) * SK + ks * 8 + (lane & 3)];
                af[mf][0] = __float_as_uint(p[0]);
                af[mf][1] = __float_as_uint(p[8 * SK]);
                af[mf][2] = __float_as_uint(p[4]);
                af[mf][3] = __float_as_uint(p[8 * SK + 4]);
            }
#pragma unroll
            for (int nf = 0; nf < 4; nf++) {
                const float* p = &Bs[(wn * 32 + nf * 8 + (lane >> 2)) * SK + ks * 8 + (lane & 3)];
                bf[nf][0] = __float_as_uint(p[0]);
                bf[nf][1] = __float_as_uint(p[4]);
            }
#pragma unroll
            for (int mf = 0; mf < 4; mf++)
#pragma unroll
                for (int nf = 0; nf < 4; nf++)
                    mma_tf32(acc[mf][nf], af[mf], bf[nf]);
        }
        __syncthreads();
    }

    const float hb = *hbias_p;
#pragma unroll
    for (int mf = 0; mf < 4; mf++) {
        int row0 = rowBase + wm * 64 + mf * 16 + (lane >> 2);
        int row1 = row0 + 8;
#pragma unroll
        for (int nf = 0; nf < 4; nf++) {
            int col = colBase + wn * 32 + nf * 8 + (lane & 3) * 2;
            float* c = acc[mf][nf];
            *(float2*)&C[(size_t)row0 * LP + col] = make_float2(c[0] + hb, c[1] + hb);
            *(float2*)&C[(size_t)row1 * LP + col] = make_float2(c[2] + hb, c[3] + hb);
        }
    }
}

// ---------------- kernel 4: per-column online softmax reduction ----------------
__global__ void col_softmax(const float* __restrict__ mask1, const float* __restrict__ mask2)
{
    const int mat = blockIdx.z;
    const float* A     = mat ? g_A2  : g_A1;
    const float* rmask = mat ? mask2 : mask1;
    const float* cmask = mat ? mask1 : mask2;
    float*       wout  = mat ? g_w2  : g_w1;

    const int b  = blockIdx.y;
    const int tx = threadIdx.x, ty = threadIdx.y;
    const int q  = blockIdx.x * 32 + tx;
    const bool qv = q < LEN;
    const float* Ab = A + (size_t)b * LP * LP;

    float m = -1e30f, den = 0.f, num = 0.f;
    if (qv) {
        for (int v = ty; v < LEN; v += 8) {
            float x = Ab[(size_t)v * LP + q];
            float w = rmask[b * LEN + v];
            float nm = fmaxf(m, x);
            float c = __expf(m - nm);
            float e = __expf(x - nm);
            den = den * c + e;
            num = num * c + w * e;
            m = nm;
        }
    }
    __shared__ float sm[8][32], sd[8][32], sn[8][32];
    sm[ty][tx] = m; sd[ty][tx] = den; sn[ty][tx] = num;
    __syncthreads();
    if (ty == 0 && qv) {
        float M = sm[0][tx], D = sd[0][tx], Nn = sn[0][tx];
#pragma unroll
        for (int i = 1; i < 8; i++) {
            float mi = sm[i][tx];
            float nm = fmaxf(M, mi);
            float c1 = __expf(M - nm), c2 = __expf(mi - nm);
            D  = D  * c1 + sd[i][tx] * c2;
            Nn = Nn * c1 + sn[i][tx] * c2;
            M = nm;
        }
        wout[b * LEN + q] = cmask[b * LEN + q] * Nn / D;
    }
}

// ---------------- kernel 5: pooled partial GEMVs ----------------
__global__ void pooled_partial()
{
    const int b = blockIdx.y, sp = blockIdx.z;
    const int k = blockIdx.x * 128 + threadIdx.x;
    const int q0 = sp * (LEN / 8), q1 = q0 + (LEN / 8);
    const float* P = g_A1Y + (size_t)b * LP * KDIM;
    const float* Q = g_A2X + (size_t)b * LP * KDIM;
    float acc = 0.f;
    for (int q = q0; q < q1; q++) acc = fmaf(g_w1[b * LEN + q], P[(size_t)q * KDIM + k], acc);
    for (int q = q0; q < q1; q++) acc = fmaf(g_w2[b * LEN + q], Q[(size_t)q * KDIM + k], acc);
    g_part[(sp * NB + b) * KDIM + k] = acc;
}

// ---------------- kernel 6: batch layernorm over B=4 ----------------
__global__ void ln_kernel(const float* __restrict__ gamma, const float* __restrict__ beta,
                          float* __restrict__ out)
{
    const int k = blockIdx.x * 256 + threadIdx.x;
    float p[NB];
#pragma unroll
    for (int b = 0; b < NB; b++) {
        float s = 0.f;
#pragma unroll
        for (int sp = 0; sp < 8; sp++) s += g_part[(sp * NB + b) * KDIM + k];
        p[b] = s * (1.0f / LEN);
    }
    float mu = 0.25f * (p[0] + p[1] + p[2] + p[3]);
    float var = 0.f;
#pragma unroll
    for (int b = 0; b < NB; b++) { float d = p[b] - mu; var += d * d; }
    var *= 0.25f;
    float inv = rsqrtf(var + 1e-5f);
#pragma unroll
    for (int b = 0; b < NB; b++)
        out[b * KDIM + k] = gamma[k] * (p[b] - mu) * inv + beta[k];
}

// ---------------- launch ----------------
extern "C" void kernel_launch(void* const* d_in, const int* in_sizes, int n_in,
                              void* d_out, int out_size)
{
    const float* X      = (const float*)d_in[0];
    const float* Y      = (const float*)d_in[1];
    const float* mask1  = (const float*)d_in[2];
    const float* mask2  = (const float*)d_in[3];
    const float* Qv     = (const float*)d_in[4];
    const float* Qg     = (const float*)d_in[5];
    const float* Qb     = (const float*)d_in[6];
    const float* Kv     = (const float*)d_in[7];
    const float* Kg     = (const float*)d_in[8];
    const float* Kb     = (const float*)d_in[9];
    const float* h_mat  = (const float*)d_in[10];
    const float* h_bias = (const float*)d_in[11];
    const float* gamma  = (const float*)d_in[12];
    const float* beta   = (const float*)d_in[13];
    float* out = (float*)d_out;

    norm_kernel<<<2, 256>>>(Qv, Qg, Kv, Kg);

    dim3 fcGrid(KDIM / 128, (NB * LP) / 128);
    fc_mma<<<fcGrid, 256>>>(X, Qv, Qb, h_mat, 0, 1, 0);  // P1  = fc(X,Q)*h
    fc_mma<<<fcGrid, 256>>>(Y, Kv, Kb, h_mat, 1, 0, 1);  // A1Y = fc(Y,K)
    fc_mma<<<fcGrid, 256>>>(Y, Qv, Qb, h_mat, 0, 1, 2);  // P2  = fc(Y,Q)*h
    fc_mma<<<fcGrid, 256>>>(X, Kv, Kb, h_mat, 1, 0, 3);  // A2X = fc(X,K)

    dim3 attGrid(LP / 128, LP / 128, NB);
    att_mma<<<attGrid, 256>>>(h_bias, 0);                // A1 = P1 @ A1Y^T + hb
    att_mma<<<attGrid, 256>>>(h_bias, 1);                // A2 = P2 @ A2X^T + hb

    col_softmax<<<dim3((LEN + 31) / 32, NB, 2), dim3(32, 8)>>>(mask1, mask2);
    pooled_partial<<<dim3(KDIM / 128, NB, 8), 128>>>();
    ln_kernel<<<KDIM / 256, 256>>>(gamma, beta, out);
}

// round 7
// speedup vs baseline: 2.0348x; 1.0734x over previous
#include <cuda_runtime.h>
#include <cstdint>
#include <cstddef>

#define NB   4
#define LEN  2000
#define LP   2048
#define KDIM 512
#define HDIM 256
#define SK   36                       // smem row stride (32 k + 4 pad) -> conflict-free
#define STAGE_F (128 * SK)            // floats per matrix per stage
#define SMEM_BYTES (4 * STAGE_F * 4)  // 2 matrices x 2 stages x STAGE_F x 4B = 73728

// ---------------- scratch (static device globals; no runtime alloc) ----------------
__device__ float g_scale[2];
__device__ float g_P1 [(size_t)NB * LP * KDIM];    // fc(X,Q)*h   (pad rows = 0)
__device__ float g_A1Y[(size_t)NB * LP * KDIM];    // fc(Y,K)
__device__ float g_P2 [(size_t)NB * LP * KDIM];    // fc(Y,Q)*h
__device__ float g_A2X[(size_t)NB * LP * KDIM];    // fc(X,K)
__device__ float g_A1 [(size_t)NB * LP * LP];      // A1[b,v,q]
__device__ float g_A2 [(size_t)NB * LP * LP];      // A2[b,q,v]
__device__ float g_w1 [NB * LEN];
__device__ float g_w2 [NB * LEN];
__device__ float g_part[8 * NB * KDIM];

// ---------------- helpers ----------------
__device__ __forceinline__ unsigned f2tf(float f) {
    unsigned u;
    asm("cvt.rna.tf32.f32 %0, %1;" : "=r"(u) : "f"(f));
    return u;
}
__device__ __forceinline__ float4 cvt4(float4 v) {
    return make_float4(__uint_as_float(f2tf(v.x)), __uint_as_float(f2tf(v.y)),
                       __uint_as_float(f2tf(v.z)), __uint_as_float(f2tf(v.w)));
}
__device__ __forceinline__ void mma_tf32(float* c, const unsigned* a, const unsigned* b) {
    asm volatile(
        "mma.sync.aligned.m16n8k8.row.col.f32.tf32.tf32.f32 "
        "{%0,%1,%2,%3}, {%4,%5,%6,%7}, {%8,%9}, {%0,%1,%2,%3};\n"
        : "+f"(c[0]), "+f"(c[1]), "+f"(c[2]), "+f"(c[3])
        : "r"(a[0]), "r"(a[1]), "r"(a[2]), "r"(a[3]), "r"(b[0]), "r"(b[1]));
}

// warp compute over one 32-K smem stage: 4 ks-steps of 16 m16n8k8 MMAs
__device__ __forceinline__ void warp_compute(const float* As, const float* Bs,
                                             int wm, int wn, int lane,
                                             float acc[4][4][4])
{
#pragma unroll
    for (int ks = 0; ks < 4; ks++) {
        unsigned af[4][4], bf[4][2];
#pragma unroll
        for (int mf = 0; mf < 4; mf++) {
            const float* p = &As[(wm * 64 + mf * 16 + (lane >> 2)) * SK + ks * 8 + (lane & 3)];
            af[mf][0] = __float_as_uint(p[0]);
            af[mf][1] = __float_as_uint(p[8 * SK]);
            af[mf][2] = __float_as_uint(p[4]);
            af[mf][3] = __float_as_uint(p[8 * SK + 4]);
        }
#pragma unroll
        for (int nf = 0; nf < 4; nf++) {
            const float* p = &Bs[(wn * 32 + nf * 8 + (lane >> 2)) * SK + ks * 8 + (lane & 3)];
            bf[nf][0] = __float_as_uint(p[0]);
            bf[nf][1] = __float_as_uint(p[4]);
        }
#pragma unroll
        for (int mf = 0; mf < 4; mf++)
#pragma unroll
            for (int nf = 0; nf < 4; nf++)
                mma_tf32(acc[mf][nf], af[mf], bf[nf]);
    }
}

// ---------------- kernel 1: weight-norm scales ----------------
__global__ void norm_kernel(const float* __restrict__ Qv, const float* __restrict__ Qg,
                            const float* __restrict__ Kv, const float* __restrict__ Kg)
{
    const float* V = blockIdx.x ? Kv : Qv;
    const float* G = blockIdx.x ? Kg : Qg;
    __shared__ float red[256];
    float s = 0.f;
    for (int i = threadIdx.x; i < KDIM * HDIM; i += 256) {
        float v = V[i];
        s += v * v;
    }
    red[threadIdx.x] = s;
    __syncthreads();
    for (int st = 128; st > 0; st >>= 1) {
        if (threadIdx.x < st) red[threadIdx.x] += red[threadIdx.x + st];
        __syncthreads();
    }
    if (threadIdx.x == 0) g_scale[blockIdx.x] = G[0] / sqrtf(red[0]);
}

// ---------------- kernel 2: all 4 FC projections fused (blockIdx.z selects) ----------------
// z=0: P1=relu(s0*X@Qv^T+Qb)*h, z=1: A1Y=relu(s1*Y@Kv^T+Kb),
// z=2: P2=relu(s0*Y@Qv^T+Qb)*h, z=3: A2X=relu(s1*X@Kv^T+Kb)
__global__ __launch_bounds__(256, 2) void fc_mma(
    const float* __restrict__ X, const float* __restrict__ Y,
    const float* __restrict__ Qv, const float* __restrict__ Kv,
    const float* __restrict__ Qb, const float* __restrict__ Kb,
    const float* __restrict__ hvec)
{
    const int z = blockIdx.z;
    const bool qSide = (z == 0) || (z == 2);
    const float* Xin  = (z == 0 || z == 3) ? X : Y;
    const float* W    = qSide ? Qv : Kv;
    const float* bias = qSide ? Qb : Kb;
    float* out = (z == 0) ? g_P1 : (z == 1) ? g_A1Y : (z == 2) ? g_P2 : g_A2X;

    extern __shared__ float sh[];
    float* AsB = sh;                   // [2][STAGE_F]
    float* BsB = sh + 2 * STAGE_F;

    const int tid  = threadIdx.x;
    const int lane = tid & 31;
    const int warp = tid >> 5;
    const int wm = warp >> 2, wn = warp & 3;
    const int rowBase = blockIdx.y * 128;
    const int colBase = blockIdx.x * 128;
    const int r  = tid >> 1;
    const int kc = (tid & 1) << 2;

    const int  m  = rowBase + r;
    const int  bb = m >> 11;
    const int  ll = m & (LP - 1);
    const bool avalid = ll < LEN;
    const float* Aptr = Xin + ((size_t)bb * LEN + ll) * HDIM + kc;
    const float* Bptr = W + (size_t)(colBase + r) * HDIM + kc;

    float acc[4][4][4];
#pragma unroll
    for (int i = 0; i < 4; i++)
#pragma unroll
        for (int j = 0; j < 4; j++)
#pragma unroll
            for (int t = 0; t < 4; t++) acc[i][j][t] = 0.f;

    float4 pa[4], pb[4];
#pragma unroll
    for (int j = 0; j < 4; j++) {
        pa[j] = avalid ? *(const float4*)(Aptr + j * 8) : make_float4(0.f, 0.f, 0.f, 0.f);
        pb[j] = *(const float4*)(Bptr + j * 8);
    }
#pragma unroll
    for (int j = 0; j < 4; j++) {
        *(float4*)&AsB[r * SK + kc + j * 8] = cvt4(pa[j]);
        *(float4*)&BsB[r * SK + kc + j * 8] = cvt4(pb[j]);
    }
    __syncthreads();

    const int NCH = HDIM / 32;
    int buf = 0;
    for (int ch = 0; ch < NCH; ch++) {
        if (ch + 1 < NCH) {
            int koff = (ch + 1) * 32;
#pragma unroll
            for (int j = 0; j < 4; j++) {
                pa[j] = avalid ? *(const float4*)(Aptr + koff + j * 8)
                               : make_float4(0.f, 0.f, 0.f, 0.f);
                pb[j] = *(const float4*)(Bptr + koff + j * 8);
            }
        }
        warp_compute(AsB + buf * STAGE_F, BsB + buf * STAGE_F, wm, wn, lane, acc);
        if (ch + 1 < NCH) {
            int nb = buf ^ 1;
#pragma unroll
            for (int j = 0; j < 4; j++) {
                *(float4*)&AsB[nb * STAGE_F + r * SK + kc + j * 8] = cvt4(pa[j]);
                *(float4*)&BsB[nb * STAGE_F + r * SK + kc + j * 8] = cvt4(pb[j]);
            }
        }
        __syncthreads();
        buf ^= 1;
    }

    const float scale = g_scale[qSide ? 0 : 1];
#pragma unroll
    for (int mf = 0; mf < 4; mf++) {
        int row0 = rowBase + wm * 64 + mf * 16 + (lane >> 2);
        int row1 = row0 + 8;
        bool v0 = (row0 & (LP - 1)) < LEN;
        bool v1 = (row1 & (LP - 1)) < LEN;
#pragma unroll
        for (int nf = 0; nf < 4; nf++) {
            int col = colBase + wn * 32 + nf * 8 + (lane & 3) * 2;
            float b0 = bias[col], b1 = bias[col + 1];
            float h0 = qSide ? hvec[col] : 1.f, h1 = qSide ? hvec[col + 1] : 1.f;
            float* c = acc[mf][nf];
            float2 o0 = make_float2(
                v0 ? fmaxf(scale * c[0] + b0, 0.f) * h0 : 0.f,
                v0 ? fmaxf(scale * c[1] + b1, 0.f) * h1 : 0.f);
            float2 o1 = make_float2(
                v1 ? fmaxf(scale * c[2] + b0, 0.f) * h0 : 0.f,
                v1 ? fmaxf(scale * c[3] + b1, 0.f) * h1 : 0.f);
            *(float2*)&out[(size_t)row0 * KDIM + col] = o0;
            *(float2*)&out[(size_t)row1 * KDIM + col] = o1;
        }
    }
}

// ---------------- kernel 3: both attention Gram matrices fused ----------------
// z = bz*2 + sel;  C[b] = A[b] @ B[b]^T + h_bias,  M=N=LP, K=KDIM (padded, no bounds)
__global__ __launch_bounds__(256, 2) void att_mma(const float* __restrict__ hbias_p)
{
    const int sel = blockIdx.z & 1;
    const int bz  = blockIdx.z >> 1;
    const float* A  = (sel ? g_P2  : g_P1)  + (size_t)bz * LP * KDIM;
    const float* Bm = (sel ? g_A2X : g_A1Y) + (size_t)bz * LP * KDIM;
    float*       C  = (sel ? g_A2  : g_A1)  + (size_t)bz * LP * LP;

    extern __shared__ float sh[];
    float* AsB = sh;
    float* BsB = sh + 2 * STAGE_F;

    const int tid  = threadIdx.x;
    const int lane = tid & 31;
    const int warp = tid >> 5;
    const int wm = warp >> 2, wn = warp & 3;
    const int rowBase = blockIdx.y * 128;
    const int colBase = blockIdx.x * 128;
    const int r  = tid >> 1;
    const int kc = (tid & 1) << 2;

    const float* Aptr = A  + (size_t)(rowBase + r) * KDIM + kc;
    const float* Bptr = Bm + (size_t)(colBase + r) * KDIM + kc;

    float acc[4][4][4];
#pragma unroll
    for (int i = 0; i < 4; i++)
#pragma unroll
        for (int j = 0; j < 4; j++)
#pragma unroll
            for (int t = 0; t < 4; t++) acc[i][j][t] = 0.f;

    float4 pa[4], pb[4];
#pragma unroll
    for (int j = 0; j < 4; j++) {
        pa[j] = *(const float4*)(Aptr + j * 8);
        pb[j] = *(const float4*)(Bptr + j * 8);
    }
#pragma unroll
    for (int j = 0; j < 4; j++) {
        *(float4*)&AsB[r * SK + kc + j * 8] = cvt4(pa[j]);
        *(float4*)&BsB[r * SK + kc + j * 8] = cvt4(pb[j]);
    }
    __syncthreads();

    const int NCH = KDIM / 32;
    int buf = 0;
    for (int ch = 0; ch < NCH; ch++) {
        if (ch + 1 < NCH) {
            int koff = (ch + 1) * 32;
#pragma unroll
            for (int j = 0; j < 4; j++) {
                pa[j] = *(const float4*)(Aptr + koff + j * 8);
                pb[j] = *(const float4*)(Bptr + koff + j * 8);
            }
        }
        warp_compute(AsB + buf * STAGE_F, BsB + buf * STAGE_F, wm, wn, lane, acc);
        if (ch + 1 < NCH) {
            int nb = buf ^ 1;
#pragma unroll
            for (int j = 0; j < 4; j++) {
                *(float4*)&AsB[nb * STAGE_F + r * SK + kc + j * 8] = cvt4(pa[j]);
                *(float4*)&BsB[nb * STAGE_F + r * SK + kc + j * 8] = cvt4(pb[j]);
            }
        }
        __syncthreads();
        buf ^= 1;
    }

    const float hb = *hbias_p;
#pragma unroll
    for (int mf = 0; mf < 4; mf++) {
        int row0 = rowBase + wm * 64 + mf * 16 + (lane >> 2);
        int row1 = row0 + 8;
#pragma unroll
        for (int nf = 0; nf < 4; nf++) {
            int col = colBase + wn * 32 + nf * 8 + (lane & 3) * 2;
            float* c = acc[mf][nf];
            *(float2*)&C[(size_t)row0 * LP + col] = make_float2(c[0] + hb, c[1] + hb);
            *(float2*)&C[(size_t)row1 * LP + col] = make_float2(c[2] + hb, c[3] + hb);
        }
    }
}

// ---------------- kernel 4: per-column online softmax reduction ----------------
__global__ void col_softmax(const float* __restrict__ mask1, const float* __restrict__ mask2)
{
    const int mat = blockIdx.z;
    const float* A     = mat ? g_A2  : g_A1;
    const float* rmask = mat ? mask2 : mask1;
    const float* cmask = mat ? mask1 : mask2;
    float*       wout  = mat ? g_w2  : g_w1;

    const int b  = blockIdx.y;
    const int tx = threadIdx.x, ty = threadIdx.y;
    const int q  = blockIdx.x * 32 + tx;
    const bool qv = q < LEN;
    const float* Ab = A + (size_t)b * LP * LP;

    float m = -1e30f, den = 0.f, num = 0.f;
    if (qv) {
        for (int v = ty; v < LEN; v += 8) {
            float x = Ab[(size_t)v * LP + q];
            float w = rmask[b * LEN + v];
            if (x > m) {
                float c = __expf(m - x);
                den = den * c + 1.f;
                num = num * c + w;
                m = x;
            } else {
                float e = __expf(x - m);
                den += e;
                num += w * e;
            }
        }
    }
    __shared__ float sm[8][32], sd[8][32], sn[8][32];
    sm[ty][tx] = m; sd[ty][tx] = den; sn[ty][tx] = num;
    __syncthreads();
    if (ty == 0 && qv) {
        float M = sm[0][tx], D = sd[0][tx], Nn = sn[0][tx];
#pragma unroll
        for (int i = 1; i < 8; i++) {
            float mi = sm[i][tx];
            float nm = fmaxf(M, mi);
            float c1 = __expf(M - nm), c2 = __expf(mi - nm);
            D  = D  * c1 + sd[i][tx] * c2;
            Nn = Nn * c1 + sn[i][tx] * c2;
            M = nm;
        }
        wout[b * LEN + q] = cmask[b * LEN + q] * Nn / D;
    }
}

// ---------------- kernel 5: pooled partial GEMVs ----------------
__global__ void pooled_partial()
{
    const int b = blockIdx.y, sp = blockIdx.z;
    const int k = blockIdx.x * 128 + threadIdx.x;
    const int q0 = sp * (LEN / 8), q1 = q0 + (LEN / 8);
    const float* P = g_A1Y + (size_t)b * LP * KDIM;
    const float* Q = g_A2X + (size_t)b * LP * KDIM;
    float acc = 0.f;
    for (int q = q0; q < q1; q++) acc = fmaf(g_w1[b * LEN + q], P[(size_t)q * KDIM + k], acc);
    for (int q = q0; q < q1; q++) acc = fmaf(g_w2[b * LEN + q], Q[(size_t)q * KDIM + k], acc);
    g_part[(sp * NB + b) * KDIM + k] = acc;
}

// ---------------- kernel 6: batch layernorm over B=4 ----------------
__global__ void ln_kernel(const float* __restrict__ gamma, const float* __restrict__ beta,
                          float* __restrict__ out)
{
    const int k = blockIdx.x * 256 + threadIdx.x;
    float p[NB];
#pragma unroll
    for (int b = 0; b < NB; b++) {
        float s = 0.f;
#pragma unroll
        for (int sp = 0; sp < 8; sp++) s += g_part[(sp * NB + b) * KDIM + k];
        p[b] = s * (1.0f / LEN);
    }
    float mu = 0.25f * (p[0] + p[1] + p[2] + p[3]);
    float var = 0.f;
#pragma unroll
    for (int b = 0; b < NB; b++) { float d = p[b] - mu; var += d * d; }
    var *= 0.25f;
    float inv = rsqrtf(var + 1e-5f);
#pragma unroll
    for (int b = 0; b < NB; b++)
        out[b * KDIM + k] = gamma[k] * (p[b] - mu) * inv + beta[k];
}

// ---------------- launch ----------------
extern "C" void kernel_launch(void* const* d_in, const int* in_sizes, int n_in,
                              void* d_out, int out_size)
{
    const float* X      = (const float*)d_in[0];
    const float* Y      = (const float*)d_in[1];
    const float* mask1  = (const float*)d_in[2];
    const float* mask2  = (const float*)d_in[3];
    const float* Qv     = (const float*)d_in[4];
    const float* Qg     = (const float*)d_in[5];
    const float* Qb     = (const float*)d_in[6];
    const float* Kv     = (const float*)d_in[7];
    const float* Kg     = (const float*)d_in[8];
    const float* Kb     = (const float*)d_in[9];
    const float* h_mat  = (const float*)d_in[10];
    const float* h_bias = (const float*)d_in[11];
    const float* gamma  = (const float*)d_in[12];
    const float* beta   = (const float*)d_in[13];
    float* out = (float*)d_out;

    static bool attr_done = false;
    if (!attr_done) {
        cudaFuncSetAttribute(fc_mma,  cudaFuncAttributeMaxDynamicSharedMemorySize, SMEM_BYTES);
        cudaFuncSetAttribute(att_mma, cudaFuncAttributeMaxDynamicSharedMemorySize, SMEM_BYTES);
        attr_done = true;
    }

    norm_kernel<<<2, 256>>>(Qv, Qg, Kv, Kg);

    dim3 fcGrid(KDIM / 128, (NB * LP) / 128, 4);
    fc_mma<<<fcGrid, 256, SMEM_BYTES>>>(X, Y, Qv, Kv, Qb, Kb, h_mat);

    dim3 attGrid(LP / 128, LP / 128, NB * 2);
    att_mma<<<attGrid, 256, SMEM_BYTES>>>(h_bias);

    col_softmax<<<dim3((LEN + 31) / 32, NB, 2), dim3(32, 8)>>>(mask1, mask2);
    pooled_partial<<<dim3(KDIM / 128, NB, 8), 128>>>();
    ln_kernel<<<KDIM / 256, 256>>>(gamma, beta, out);
}